// round 15
// baseline (speedup 1.0000x reference)
#include <cuda_runtime.h>
#include <cuda_fp16.h>
#include <cstdint>

// ---------------------------------------------------------------------------
// Problem constants
// ---------------------------------------------------------------------------
#define BATCH 16
#define DDIM  1024
#define NMAX  8192
#define MTOT  (BATCH * NMAX)     // 131072 rows
#define MT    1024               // M tiles of 128 rows
#define NT2   16                 // N sub-tiles of 64 cols

// fp32 constants mirroring the reference's fp32 math
#define TWO_PI_F 6.28318548202514648438f
#define PI2_HI   6.28318548202514648438f
#define PI2_LO  -1.74845553e-7f
#define INV_2PI  0.15915494309189535f

// W images: 8 x 32KB (128 d-rows x 128 fp16 each, swizzled 256B rows) = 256KB.
__device__ __align__(1024) static unsigned char g_B[(size_t)8 * 32768];

// ---------------------------------------------------------------------------
// Helpers
// ---------------------------------------------------------------------------
__device__ __forceinline__ uint32_t smem_u32(const void* p) {
    uint32_t a;
    asm("{ .reg .u64 t; cvta.to.shared.u64 t, %1; cvt.u32.u64 %0, t; }" : "=r"(a) : "l"(p));
    return a;
}

__device__ __forceinline__ unsigned sw(unsigned row, unsigned kb) {
    return row * 256u + (kb ^ ((row & 7u) << 4));
}

__device__ __forceinline__ unsigned packh2(__half a, __half b) {
    return (unsigned)__half_as_ushort(a) | ((unsigned)__half_as_ushort(b) << 16);
}

#define CP_ASYNC16(sm, gp) \
    asm volatile("cp.async.cg.shared.global [%0], [%1], 16;" :: "r"(sm), "l"(gp))
#define CP_ASYNC_COMMIT() asm volatile("cp.async.commit_group;" ::: "memory")
#define CP_ASYNC_WAIT0()  asm volatile("cp.async.wait_group 0;" ::: "memory")

#define LDSM_X4(r, addr) \
    asm volatile("ldmatrix.sync.aligned.m8n8.x4.shared.b16 {%0,%1,%2,%3}, [%4];" \
        : "=r"((r)[0]), "=r"((r)[1]), "=r"((r)[2]), "=r"((r)[3]) : "r"(addr))

#define MMA16816(c, a, b0v, b1v) \
    asm volatile("mma.sync.aligned.m16n8k16.row.col.f32.f16.f16.f32 " \
        "{%0,%1,%2,%3}, {%4,%5,%6,%7}, {%8,%9}, {%0,%1,%2,%3};" \
        : "+f"((c)[0]), "+f"((c)[1]), "+f"((c)[2]), "+f"((c)[3]) \
        : "r"((a)[0]), "r"((a)[1]), "r"((a)[2]), "r"((a)[3]), "r"(b0v), "r"(b1v))

#define STS_V4F(addr, a, bb, c, d) \
    asm volatile("st.shared.v4.f32 [%0], {%1, %2, %3, %4};" \
        :: "r"(addr), "f"(a), "f"(bb), "f"(c), "f"(d) : "memory")
#define STG_V4Z(ptr) \
    asm volatile("st.global.v4.b32 [%0], {%1, %1, %1, %1};" :: "l"(ptr), "r"(0u) : "memory")

// 1D bulk async copy shared -> global (sm_90 baseline PTX, NOT an 'a' feature)
#define BULK_S2G(gptr, saddr, bytes) \
    asm volatile("cp.async.bulk.global.shared::cta.bulk_group [%0], [%1], %2;" \
        :: "l"(gptr), "r"(saddr), "r"((uint32_t)(bytes)) : "memory")
#define BULK_COMMIT() asm volatile("cp.async.bulk.commit_group;" ::: "memory")
#define BULK_WAIT_READ0() asm volatile("cp.async.bulk.wait_group.read 0;" ::: "memory")
#define FENCE_PROXY_ASYNC() asm volatile("fence.proxy.async.shared::cta;" ::: "memory")

// Butterfly stage over 4 float2 slots: swap lane-bit K with slot-bit 0.
template<int K>
__device__ __forceinline__ void xstage4(float2* v, int lane) {
    const bool hi = ((lane >> K) & 1) != 0;
    #pragma unroll
    for (int i0 = 0; i0 < 4; i0 += 2) {
        const int i1 = i0 + 1;
        float sx = hi ? v[i0].x : v[i1].x;
        float sy = hi ? v[i0].y : v[i1].y;
        float rx = __shfl_xor_sync(0xffffffffu, sx, 1 << K);
        float ry = __shfl_xor_sync(0xffffffffu, sy, 1 << K);
        if (hi) { v[i0].x = rx; v[i0].y = ry; }
        else    { v[i1].x = rx; v[i1].y = ry; }
    }
}

// ---------------------------------------------------------------------------
// W prep: W[1024,128] fp32 -> fp16, swizzled tile images
// ---------------------------------------------------------------------------
__global__ void __launch_bounds__(256) wprep_kernel(const float* __restrict__ W)
{
    int idx  = blockIdx.x * 256 + threadIdx.x;     // < 8*128*16 = 16384
    int nt   = idx >> 11;
    int rem  = idx & 2047;
    int drow = rem >> 4;
    int kg   = rem & 15;

    const float* wr = W + (size_t)(nt * 128 + drow) * 128 + kg * 8;
    unsigned hi[4];
    #pragma unroll
    for (int j = 0; j < 4; ++j)
        hi[j] = packh2(__float2half_rn(wr[2 * j]), __float2half_rn(wr[2 * j + 1]));
    unsigned char* base = g_B + (size_t)nt * 32768;
    *reinterpret_cast<uint4*>(base + sw((unsigned)drow, (unsigned)kg * 16)) =
        make_uint4(hi[0], hi[1], hi[2], hi[3]);
}

// ---------------------------------------------------------------------------
// Fused gen + GEMM (+ mask tail). Single-pass fp16. 2 CTAs/SM.
// CTA tile 128x64, warp tile 32x32. Epilogue: butterfly -> STS staging ->
// cp.async.bulk S2G (bypasses the per-warp STG/L1tex global-store path).
// smem: A [0,32K), B buf0 [32K,48K), B buf1 [48K,64K), stage [64K, 64K+34816)
// ---------------------------------------------------------------------------
#define SMEM_A       0
#define SMEM_B       32768
#define SMEM_STAGE   65536
#define STAGE_STRIDE 272                 // 16-aligned, minimal STS conflicts
#define SMEM_TOTAL   (SMEM_STAGE + 128 * STAGE_STRIDE)   // 100352

__global__ void __launch_bounds__(256, 2)
gemm_kernel(const int* __restrict__ lengths, float* __restrict__ out,
            float* __restrict__ mask_out)
{
    extern __shared__ unsigned char smem[];
    const uint32_t sb = smem_u32(smem);
    const int tid  = threadIdx.x;
    const int lane = tid & 31;
    const int wid  = tid >> 5;

    const int mtile = blockIdx.x;          // 0..1023
    const int b     = mtile >> 6;
    const int n0    = (mtile & 63) * 128;
    const int phase = mtile & 15;

    const int   L  = lengths[b];
    const float Lf = (float)L;

    // ---- Mask tail for this tile's 128 rows (fused) ----
    if (mask_out != nullptr && tid < 128) {
        int n = n0 + tid;
        mask_out[(size_t)mtile * 128 + tid] = (n < L) ? 1.0f : 0.0f;
    }

    // ---- Fast path: fully-masked tile -> pure zero fill ----
    if (n0 >= L) {
        float* base = out + (size_t)mtile * 128 * DDIM;
        #pragma unroll 4
        for (int i = tid; i < (128 * DDIM) / 4; i += 256)
            STG_V4Z(base + (size_t)i * 4);
        return;
    }

    // ---- Prologue: async-copy first B subtile (16KB) ----
    {
        const unsigned char* gB0 = g_B + (size_t)phase * 16384;
        #pragma unroll
        for (int it = 0; it < 4; ++it)
            CP_ASYNC16(sb + SMEM_B + it * 4096 + tid * 16, gB0 + it * 4096 + tid * 16);
        CP_ASYNC_COMMIT();
    }

    // ---- Generate feats tile (fp16, masked, swizzled) via rotation recurrence ----
    {
        const int row0 = tid >> 4;         // 0..15
        const int kg   = tid & 15;
        const float nf = (float)(n0 + row0);

        float c[4], s[4], C[4], S[4];
        #pragma unroll
        for (int j = 0; j < 4; ++j) {
            int k = kg * 4 + j + 1;
            float Delta = (TWO_PI_F * (float)k) / Lf;
            float theta = nf * Delta;
            float q = rintf(theta * INV_2PI);
            float r = fmaf(-q, PI2_HI, theta);
            r       = fmaf(-q, PI2_LO, r);
            __sincosf(r, &s[j], &c[j]);
            __sincosf(16.0f * Delta, &S[j], &C[j]);
        }

        #pragma unroll
        for (int it = 0; it < 8; ++it) {
            int row = row0 + it * 16;
            int n   = n0 + row;
            float m = (n < L) ? 0.125f : 0.0f;
            unsigned hi[4];
            #pragma unroll
            for (int j = 0; j < 4; ++j)
                hi[j] = packh2(__float2half_rn(c[j] * m), __float2half_rn(s[j] * m));
            *reinterpret_cast<uint4*>(smem + SMEM_A + sw((unsigned)row, (unsigned)kg * 16)) =
                make_uint4(hi[0], hi[1], hi[2], hi[3]);
            #pragma unroll
            for (int j = 0; j < 4; ++j) {
                float cn = fmaf(c[j], C[j], -s[j] * S[j]);
                float sn = fmaf(s[j], C[j],  c[j] * S[j]);
                c[j] = cn; s[j] = sn;
            }
        }
    }

    // ---- Per-thread ldmatrix address components (warp tile 32 rows x 32 cols) ----
    const unsigned m0 = (unsigned)(wid >> 1) * 32u;   // warp M base (0,32,64,96)
    const unsigned nb = (unsigned)(wid & 1) * 32u;    // warp N base within 64-col tile
    const unsigned aRow  = m0 + (unsigned)(lane & 15);
    const unsigned aXr   = (aRow & 7u) << 4;
    const unsigned aC0   = (unsigned)(lane & 16);
    const uint32_t aBase0 = sb + SMEM_A + aRow * 256u;
    const uint32_t aBase1 = aBase0 + 16u * 256u;
    const unsigned bRl = (unsigned)((lane & 7) + ((lane & 16) ? 8 : 0));
    const unsigned bXr = (bRl & 7u) << 4;
    const unsigned bC0 = (unsigned)((lane & 8) ? 16 : 0);

    // Staging address components: lane lam writes 16B at col-offset 16*lam (+64 per g)
    const int q   = lane >> 2;
    const int lam = lane & 3;
    const uint32_t stageW = sb + SMEM_STAGE + (unsigned)(m0 * STAGE_STRIDE)
                          + nb * 4u + (unsigned)lam * 16u;
    // Bulk copy: thread tid handles output row tid of the tile (256B segment).
    const uint32_t stageR = sb + SMEM_STAGE + (unsigned)tid * STAGE_STRIDE;
    const size_t   outRow = ((size_t)(mtile * 128) + tid) * DDIM;

    __syncthreads();   // A tile ready

    for (int it = 0; it < NT2; ++it) {
        const int nt = (it + phase) & 15;

        CP_ASYNC_WAIT0();
        __syncthreads();   // B subtile ready

        if (it + 1 < NT2) {
            const unsigned char* gBn = g_B + (size_t)(((it + 1 + phase) & 15)) * 16384;
            uint32_t bo = sb + SMEM_B + (unsigned)((it + 1) & 1) * 16384u;
            #pragma unroll
            for (int i2 = 0; i2 < 4; ++i2)
                CP_ASYNC16(bo + i2 * 4096 + tid * 16, gBn + i2 * 4096 + tid * 16);
            CP_ASYNC_COMMIT();
        }

        const uint32_t bBase = sb + SMEM_B + (unsigned)(it & 1) * 16384u;

        float acc[8][4];
        #pragma unroll
        for (int i = 0; i < 8; ++i)
            #pragma unroll
            for (int j = 0; j < 4; ++j) acc[i][j] = 0.0f;

        #pragma unroll
        for (int ks = 0; ks < 8; ++ks) {
            const unsigned akb = ((unsigned)ks * 32u + aC0) ^ aXr;
            uint32_t a0[4], a1[4];
            LDSM_X4(a0, aBase0 + akb);
            LDSM_X4(a1, aBase1 + akb);

            const unsigned bkb = ((unsigned)ks * 32u + bC0) ^ bXr;
            #pragma unroll
            for (int np = 0; np < 2; ++np) {
                uint32_t bh[4];
                LDSM_X4(bh, bBase + (nb + np * 16u + bRl) * 256u + bkb);
                MMA16816(acc[np * 2],         a0, bh[0], bh[1]);
                MMA16816(acc[np * 2 + 1],     a0, bh[2], bh[3]);
                MMA16816(acc[4 + np * 2],     a1, bh[0], bh[1]);
                MMA16816(acc[4 + np * 2 + 1], a1, bh[2], bh[3]);
            }
        }

        // ---- Epilogue: staging must be free (prev iter's bulk reads done) ----
        BULK_WAIT_READ0();
        __syncthreads();

        // Butterfly transpose -> STS.128 into linear-row staging.
        // Row r = m0 + 16h + 8ss + q; lane lam holds cols 4lam (+16 per g).
        #pragma unroll
        for (int h = 0; h < 2; ++h) {
            #pragma unroll
            for (int ssv = 0; ssv < 2; ++ssv) {
                float2 v[4];
                #pragma unroll
                for (int t = 0; t < 4; ++t) {
                    v[t].x = acc[4 * h + t][2 * ssv];
                    v[t].y = acc[4 * h + t][2 * ssv + 1];
                }
                xstage4<1>(v, lane);
                xstage4<0>(v, lane);
                uint32_t sp = stageW + (unsigned)((16 * h + 8 * ssv + q) * STAGE_STRIDE);
                STS_V4F(sp,      v[0].x, v[0].y, v[1].x, v[1].y);
                STS_V4F(sp + 64, v[2].x, v[2].y, v[3].x, v[3].y);
            }
        }

        FENCE_PROXY_ASYNC();
        __syncthreads();   // all STS visible to the async proxy

        // 128 threads each issue one 256B bulk copy (their output row segment).
        if (tid < 128) {
            BULK_S2G(out + outRow + (size_t)nt * 64, stageR, 256);
            BULK_COMMIT();
        }
    }

    // Drain the last tile's bulk copies before exit.
    BULK_WAIT_READ0();
    asm volatile("cp.async.bulk.wait_group 0;" ::: "memory");
}

// ---------------------------------------------------------------------------
extern "C" void kernel_launch(void* const* d_in, const int* in_sizes, int n_in,
                              void* d_out, int out_size)
{
    const int*   lengths = (const int*)d_in[0];
    const float* W       = (const float*)d_in[1];
    float*       out     = (float*)d_out;
    (void)in_sizes; (void)n_in;

    cudaFuncSetAttribute(gemm_kernel,
                         cudaFuncAttributeMaxDynamicSharedMemorySize, SMEM_TOTAL);

    long long pos_elems = (long long)MTOT * DDIM;
    float* mask_ptr = ((long long)out_size >= pos_elems + (long long)MTOT)
                          ? (out + pos_elems) : nullptr;

    wprep_kernel<<<64, 256>>>(W);
    gemm_kernel<<<MT, 256, SMEM_TOTAL>>>(lengths, out, mask_ptr);
}

// round 16
// speedup vs baseline: 1.2347x; 1.2347x over previous
#include <cuda_runtime.h>
#include <cuda_fp16.h>
#include <cstdint>

// ---------------------------------------------------------------------------
// Problem constants
// ---------------------------------------------------------------------------
#define BATCH 16
#define DDIM  1024
#define NMAX  8192
#define MTOT  (BATCH * NMAX)     // 131072 rows
#define MT    1024               // M tiles of 128 rows
#define NT4   4                  // N swaths of 256 cols

// fp32 constants mirroring the reference's fp32 math
#define TWO_PI_F 6.28318548202514648438f
#define PI2_HI   6.28318548202514648438f
#define PI2_LO  -1.74845553e-7f
#define INV_2PI  0.15915494309189535f

// W images: 8 x 32KB (128 d-rows x 128 fp16 each, swizzled 256B rows) = 256KB.
// A 256-col swath j (j=0..3) is the contiguous 64KB chunk at g_B + j*65536.
__device__ __align__(1024) static unsigned char g_B[(size_t)8 * 32768];

// ---------------------------------------------------------------------------
// Helpers
// ---------------------------------------------------------------------------
__device__ __forceinline__ uint32_t smem_u32(const void* p) {
    uint32_t a;
    asm("{ .reg .u64 t; cvta.to.shared.u64 t, %1; cvt.u32.u64 %0, t; }" : "=r"(a) : "l"(p));
    return a;
}

__device__ __forceinline__ unsigned sw(unsigned row, unsigned kb) {
    return row * 256u + (kb ^ ((row & 7u) << 4));
}

__device__ __forceinline__ unsigned packh2(__half a, __half b) {
    return (unsigned)__half_as_ushort(a) | ((unsigned)__half_as_ushort(b) << 16);
}

#define CP_ASYNC16(sm, gp) \
    asm volatile("cp.async.cg.shared.global [%0], [%1], 16;" :: "r"(sm), "l"(gp))
#define CP_ASYNC_COMMIT() asm volatile("cp.async.commit_group;" ::: "memory")
#define CP_ASYNC_WAIT0()  asm volatile("cp.async.wait_group 0;" ::: "memory")

#define LDSM_X4(r, addr) \
    asm volatile("ldmatrix.sync.aligned.m8n8.x4.shared.b16 {%0,%1,%2,%3}, [%4];" \
        : "=r"((r)[0]), "=r"((r)[1]), "=r"((r)[2]), "=r"((r)[3]) : "r"(addr))

#define MMA16816(c, a, b0v, b1v) \
    asm volatile("mma.sync.aligned.m16n8k16.row.col.f32.f16.f16.f32 " \
        "{%0,%1,%2,%3}, {%4,%5,%6,%7}, {%8,%9}, {%0,%1,%2,%3};" \
        : "+f"((c)[0]), "+f"((c)[1]), "+f"((c)[2]), "+f"((c)[3]) \
        : "r"((a)[0]), "r"((a)[1]), "r"((a)[2]), "r"((a)[3]), "r"(b0v), "r"(b1v))

#define STG_CS_V4F(ptr, a, bb, c, d) \
    asm volatile("st.global.cs.v4.f32 [%0], {%1, %2, %3, %4};" \
        :: "l"(ptr), "f"(a), "f"(bb), "f"(c), "f"(d) : "memory")
#define STG_CS_V4Z(ptr) \
    asm volatile("st.global.cs.v4.b32 [%0], {%1, %1, %1, %1};" :: "l"(ptr), "r"(0u) : "memory")

// Butterfly stage over NS float2 slots: swap lane-bit K with slot-bit M.
template<int K, int M, int NS>
__device__ __forceinline__ void xstage(float2* v, int lane) {
    const bool hi = ((lane >> K) & 1) != 0;
    #pragma unroll
    for (int i0 = 0; i0 < NS; ++i0) {
        if (i0 & (1 << M)) continue;
        const int i1 = i0 | (1 << M);
        float sx = hi ? v[i0].x : v[i1].x;
        float sy = hi ? v[i0].y : v[i1].y;
        float rx = __shfl_xor_sync(0xffffffffu, sx, 1 << K);
        float ry = __shfl_xor_sync(0xffffffffu, sy, 1 << K);
        if (hi) { v[i0].x = rx; v[i0].y = ry; }
        else    { v[i1].x = rx; v[i1].y = ry; }
    }
}

// ---------------------------------------------------------------------------
// W prep: W[1024,128] fp32 -> fp16, swizzled tile images (unchanged)
// ---------------------------------------------------------------------------
__global__ void __launch_bounds__(256) wprep_kernel(const float* __restrict__ W)
{
    int idx  = blockIdx.x * 256 + threadIdx.x;     // < 8*128*16 = 16384
    int nt   = idx >> 11;
    int rem  = idx & 2047;
    int drow = rem >> 4;
    int kg   = rem & 15;

    const float* wr = W + (size_t)(nt * 128 + drow) * 128 + kg * 8;
    unsigned hi[4];
    #pragma unroll
    for (int j = 0; j < 4; ++j)
        hi[j] = packh2(__float2half_rn(wr[2 * j]), __float2half_rn(wr[2 * j + 1]));
    unsigned char* base = g_B + (size_t)nt * 32768;
    *reinterpret_cast<uint4*>(base + sw((unsigned)drow, (unsigned)kg * 16)) =
        make_uint4(hi[0], hi[1], hi[2], hi[3]);
}

// ---------------------------------------------------------------------------
// Fused gen + GEMM (+ mask tail). Single-pass fp16. 512 threads, 1 CTA/SM.
// CTA tile 128 x 256-col swath per iteration (4 iterations): each visit writes
// a full 1KB contiguous chunk per output row -> one DRAM page activation/visit.
// Warp grid 4(M) x 4(N); warp tile 32 x 64 (identical math to the 128-col best).
// smem: A [0,32K), B buf0 [32K,96K), B buf1 [96K,160K)
// ---------------------------------------------------------------------------
#define SMEM_A     0
#define SMEM_B     32768
#define SMEM_TOTAL 163840

__global__ void __launch_bounds__(512, 1)
gemm_kernel(const int* __restrict__ lengths, float* __restrict__ out,
            float* __restrict__ mask_out)
{
    extern __shared__ unsigned char smem[];
    const uint32_t sb = smem_u32(smem);
    const int tid  = threadIdx.x;
    const int lane = tid & 31;
    const int wid  = tid >> 5;              // 0..15

    const int mtile = blockIdx.x;           // 0..1023
    const int b     = mtile >> 6;
    const int n0    = (mtile & 63) * 128;
    const int phase = mtile & 3;            // spread B-swath reads across L2

    const int   L  = lengths[b];
    const float Lf = (float)L;

    // ---- Mask tail for this tile's 128 rows (fused) ----
    if (mask_out != nullptr && tid < 128) {
        int n = n0 + tid;
        mask_out[(size_t)mtile * 128 + tid] = (n < L) ? 1.0f : 0.0f;
    }

    // ---- Fast path: fully-masked tile -> pure zero fill ----
    if (n0 >= L) {
        float* base = out + (size_t)mtile * 128 * DDIM;
        #pragma unroll 4
        for (int i = tid; i < (128 * DDIM) / 4; i += 512)
            STG_CS_V4Z(base + (size_t)i * 4);
        return;
    }

    // ---- Prologue: async-copy first B swath (64KB, 8 passes x 512 x 16B) ----
    {
        const unsigned char* gB0 = g_B + (size_t)phase * 65536;
        #pragma unroll
        for (int i2 = 0; i2 < 8; ++i2)
            CP_ASYNC16(sb + SMEM_B + i2 * 8192 + tid * 16, gB0 + i2 * 8192 + tid * 16);
        CP_ASYNC_COMMIT();
    }

    // ---- Generate feats tile: threads 0-255, EXACT code of the 128.4us best
    //      (A tile bit-identical; warps 8-15 just wait at the barrier) ----
    if (tid < 256) {
        const int row0 = tid >> 4;          // 0..15
        const int kg   = tid & 15;
        const float nf = (float)(n0 + row0);

        float c[4], s[4], C[4], S[4];
        #pragma unroll
        for (int j = 0; j < 4; ++j) {
            int k = kg * 4 + j + 1;
            float Delta = (TWO_PI_F * (float)k) / Lf;
            float theta = nf * Delta;
            float q = rintf(theta * INV_2PI);
            float r = fmaf(-q, PI2_HI, theta);
            r       = fmaf(-q, PI2_LO, r);
            __sincosf(r, &s[j], &c[j]);
            __sincosf(16.0f * Delta, &S[j], &C[j]);
        }

        #pragma unroll
        for (int it = 0; it < 8; ++it) {
            int row = row0 + it * 16;
            int n   = n0 + row;
            float m = (n < L) ? 0.125f : 0.0f;
            unsigned hi[4];
            #pragma unroll
            for (int j = 0; j < 4; ++j)
                hi[j] = packh2(__float2half_rn(c[j] * m), __float2half_rn(s[j] * m));
            *reinterpret_cast<uint4*>(smem + SMEM_A + sw((unsigned)row, (unsigned)kg * 16)) =
                make_uint4(hi[0], hi[1], hi[2], hi[3]);
            #pragma unroll
            for (int j = 0; j < 4; ++j) {
                float cn = fmaf(c[j], C[j], -s[j] * S[j]);
                float sn = fmaf(s[j], C[j],  c[j] * S[j]);
                c[j] = cn; s[j] = sn;
            }
        }
    }

    // ---- Per-thread ldmatrix address components ----
    // Warp grid: mw = wid>>2 (M base 32*mw), nw = wid&3 (64-col slice of swath).
    const unsigned m0    = (unsigned)(wid >> 2) * 32u;
    const unsigned nw    = (unsigned)(wid & 3);
    const unsigned bhalf = nw >> 1;                 // which 32KB g_B tile of the swath
    const unsigned nb2   = (nw & 1) * 64u;          // 64-col offset within that tile
    const unsigned aRow  = m0 + (unsigned)(lane & 15);
    const unsigned aXr   = (aRow & 7u) << 4;
    const unsigned aC0   = (unsigned)(lane & 16);
    const uint32_t aBase0 = sb + SMEM_A + aRow * 256u;
    const uint32_t aBase1 = aBase0 + 16u * 256u;
    const unsigned bRl = (unsigned)((lane & 7) + ((lane & 16) ? 8 : 0));
    const unsigned bXr = (bRl & 7u) << 4;
    const unsigned bC0 = (unsigned)((lane & 8) ? 16 : 0);

    __syncthreads();   // A tile + first B swath ordering point

    for (int it = 0; it < NT4; ++it) {
        const int nt = (it + phase) & 3;    // actual 256-col swath index

        CP_ASYNC_WAIT0();
        __syncthreads();   // B swath ready; all warps done with other buffer

        if (it + 1 < NT4) {
            const unsigned char* gBn = g_B + (size_t)(((it + 1 + phase) & 3)) * 65536;
            uint32_t bo = sb + SMEM_B + (unsigned)((it + 1) & 1) * 65536u;
            #pragma unroll
            for (int i2 = 0; i2 < 8; ++i2)
                CP_ASYNC16(bo + i2 * 8192 + tid * 16, gBn + i2 * 8192 + tid * 16);
            CP_ASYNC_COMMIT();
        }

        const uint32_t bTile = sb + SMEM_B + (unsigned)(it & 1) * 65536u
                             + bhalf * 32768u;

        // acc[0..7]: m-frag 0 (rows m0+q, m0+8+q), acc[8..15]: m-frag 1 (+16).
        // acc[8h+i] covers cols [8i, 8i+8) of the warp's 64-col slice.
        float acc[16][4];
        #pragma unroll
        for (int i = 0; i < 16; ++i)
            #pragma unroll
            for (int j = 0; j < 4; ++j) acc[i][j] = 0.0f;

        #pragma unroll
        for (int ks = 0; ks < 8; ++ks) {
            const unsigned akb = ((unsigned)ks * 32u + aC0) ^ aXr;
            uint32_t a0[4], a1[4];
            LDSM_X4(a0, aBase0 + akb);
            LDSM_X4(a1, aBase1 + akb);

            const unsigned bkb = ((unsigned)ks * 32u + bC0) ^ bXr;
            #pragma unroll
            for (int np = 0; np < 4; ++np) {
                uint32_t bh[4];
                LDSM_X4(bh, bTile + (nb2 + np * 16u + bRl) * 256u + bkb);
                MMA16816(acc[np * 2],         a0, bh[0], bh[1]);
                MMA16816(acc[np * 2 + 1],     a0, bh[2], bh[3]);
                MMA16816(acc[8 + np * 2],     a1, bh[0], bh[1]);
                MMA16816(acc[8 + np * 2 + 1], a1, bh[2], bh[3]);
            }
        }

        // ---- Epilogue: butterfly transpose -> STG.128. The 4 N-warps of each
        // row group write 4x256B = the full 1KB swath of that row this iteration.
        {
            const int q   = lane >> 2;
            const int lam = lane & 3;
            const size_t rowbase = ((size_t)(mtile * 128) + m0) * DDIM
                                 + (size_t)nt * 256 + nw * 64 + 4 * lam;
            #pragma unroll
            for (int h = 0; h < 2; ++h) {
                #pragma unroll
                for (int ssv = 0; ssv < 2; ++ssv) {
                    float2 v[8];
                    #pragma unroll
                    for (int t = 0; t < 8; ++t) {
                        v[t].x = acc[8 * h + t][2 * ssv];
                        v[t].y = acc[8 * h + t][2 * ssv + 1];
                    }
                    xstage<1, 0, 8>(v, lane);
                    xstage<0, 0, 8>(v, lane);
                    float* rp = out + rowbase + (size_t)(16 * h + 8 * ssv + q) * DDIM;
                    #pragma unroll
                    for (int g = 0; g < 4; ++g)
                        STG_CS_V4F(rp + 16 * g,
                                   v[2 * g].x, v[2 * g].y,
                                   v[2 * g + 1].x, v[2 * g + 1].y);
                }
            }
        }
    }
}

// ---------------------------------------------------------------------------
extern "C" void kernel_launch(void* const* d_in, const int* in_sizes, int n_in,
                              void* d_out, int out_size)
{
    const int*   lengths = (const int*)d_in[0];
    const float* W       = (const float*)d_in[1];
    float*       out     = (float*)d_out;
    (void)in_sizes; (void)n_in;

    cudaFuncSetAttribute(gemm_kernel,
                         cudaFuncAttributeMaxDynamicSharedMemorySize, SMEM_TOTAL);

    long long pos_elems = (long long)MTOT * DDIM;
    float* mask_ptr = ((long long)out_size >= pos_elems + (long long)MTOT)
                          ? (out + pos_elems) : nullptr;

    wprep_kernel<<<64, 256>>>(W);
    gemm_kernel<<<MT, 512, SMEM_TOTAL>>>(lengths, out, mask_ptr);
}

// round 17
// speedup vs baseline: 1.3323x; 1.0791x over previous
#include <cuda_runtime.h>
#include <cuda_fp16.h>
#include <cstdint>

// ---------------------------------------------------------------------------
// Problem constants
// ---------------------------------------------------------------------------
#define BATCH 16
#define DDIM  1024
#define NMAX  8192
#define MTOT  (BATCH * NMAX)     // 131072 rows
#define MT    1024               // M tiles of 128 rows
#define NT    8                  // N tiles of 128 cols

// fp32 constants mirroring the reference's fp32 math
#define TWO_PI_F 6.28318548202514648438f
#define PI2_HI   6.28318548202514648438f
#define PI2_LO  -1.74845553e-7f
#define INV_2PI  0.15915494309189535f

// W images: per ntile 32KB (128 d-rows x 128 fp16, swizzled 256B rows). 256KB, L2-resident.
__device__ __align__(1024) static unsigned char g_B[(size_t)NT * 32768];

// W-ready synchronization (self-resetting across graph replays).
__device__ int g_flag;   // # of wprep chunks published (0..64)
__device__ int g_done;   // # of blocks finished this launch (0..1024)

// ---------------------------------------------------------------------------
// Helpers
// ---------------------------------------------------------------------------
__device__ __forceinline__ uint32_t smem_u32(const void* p) {
    uint32_t a;
    asm("{ .reg .u64 t; cvta.to.shared.u64 t, %1; cvt.u32.u64 %0, t; }" : "=r"(a) : "l"(p));
    return a;
}

__device__ __forceinline__ unsigned sw(unsigned row, unsigned kb) {
    return row * 256u + (kb ^ ((row & 7u) << 4));
}

__device__ __forceinline__ unsigned packh2(__half a, __half b) {
    return (unsigned)__half_as_ushort(a) | ((unsigned)__half_as_ushort(b) << 16);
}

#define CP_ASYNC16(sm, gp) \
    asm volatile("cp.async.cg.shared.global [%0], [%1], 16;" :: "r"(sm), "l"(gp))
#define CP_ASYNC_COMMIT() asm volatile("cp.async.commit_group;" ::: "memory")
#define CP_ASYNC_WAIT0()  asm volatile("cp.async.wait_group 0;" ::: "memory")

#define LDSM_X4(r, addr) \
    asm volatile("ldmatrix.sync.aligned.m8n8.x4.shared.b16 {%0,%1,%2,%3}, [%4];" \
        : "=r"((r)[0]), "=r"((r)[1]), "=r"((r)[2]), "=r"((r)[3]) : "r"(addr))

#define MMA16816(c, a, b0v, b1v) \
    asm volatile("mma.sync.aligned.m16n8k16.row.col.f32.f16.f16.f32 " \
        "{%0,%1,%2,%3}, {%4,%5,%6,%7}, {%8,%9}, {%0,%1,%2,%3};" \
        : "+f"((c)[0]), "+f"((c)[1]), "+f"((c)[2]), "+f"((c)[3]) \
        : "r"((a)[0]), "r"((a)[1]), "r"((a)[2]), "r"((a)[3]), "r"(b0v), "r"(b1v))

#define STG_CS_V4F(ptr, a, bb, c, d) \
    asm volatile("st.global.cs.v4.f32 [%0], {%1, %2, %3, %4};" \
        :: "l"(ptr), "f"(a), "f"(bb), "f"(c), "f"(d) : "memory")
#define STG_CS_V4Z(ptr) \
    asm volatile("st.global.cs.v4.b32 [%0], {%1, %1, %1, %1};" :: "l"(ptr), "r"(0u) : "memory")

// Butterfly stage over 8 float2 slots: swap lane-bit K with slot-bit 0.
template<int K>
__device__ __forceinline__ void xstage8(float2* v, int lane) {
    const bool hi = ((lane >> K) & 1) != 0;
    #pragma unroll
    for (int i0 = 0; i0 < 8; i0 += 2) {
        const int i1 = i0 + 1;
        float sx = hi ? v[i0].x : v[i1].x;
        float sy = hi ? v[i0].y : v[i1].y;
        float rx = __shfl_xor_sync(0xffffffffu, sx, 1 << K);
        float ry = __shfl_xor_sync(0xffffffffu, sy, 1 << K);
        if (hi) { v[i0].x = rx; v[i0].y = ry; }
        else    { v[i1].x = rx; v[i1].y = ry; }
    }
}

// Last-block-out bookkeeping: resets the flags so every graph replay is identical.
__device__ __forceinline__ void block_finish(int tid) {
    __syncthreads();
    if (tid == 0) {
        int d = atomicAdd(&g_done, 1);
        if (d == MT - 1) {            // last block this launch
            atomicExch(&g_flag, 0);
            atomicExch(&g_done, 0);
        }
    }
}

// ---------------------------------------------------------------------------
// Fused wprep + gen + GEMM (+ mask tail). Single-pass fp16. 2 CTAs/SM.
// Blocks 0-63 (batch 0: never fully masked) publish W chunk -> g_flag.
// All blocks: gen feats (overlaps wprep wave) -> wait flag -> B pipeline.
// GEMM identical to the 128.4us best: warp tile 32x64, NT=8, butterfly+STG.cs.
// smem: A [0,32K), B buf0 [32K,64K), B buf1 [64K,96K)
// ---------------------------------------------------------------------------
#define SMEM_A     0
#define SMEM_B     32768
#define SMEM_TOTAL 98304

__global__ void __launch_bounds__(256, 2)
gemm_kernel(const int* __restrict__ lengths, const float* __restrict__ W,
            float* __restrict__ out, float* __restrict__ mask_out)
{
    extern __shared__ unsigned char smem[];
    const uint32_t sb = smem_u32(smem);
    const int tid  = threadIdx.x;
    const int lane = tid & 31;
    const int wid  = tid >> 5;

    const int mtile = blockIdx.x;          // 0..1023
    const int b     = mtile >> 6;
    const int n0    = (mtile & 63) * 128;
    const int phase = mtile & 7;           // desync co-resident CTAs (148 % 8 == 4)

    const int   L  = lengths[b];
    const float Lf = (float)L;

    // ---- Fused W prep: blocks 0-63 convert their 1/64 chunk of W ----
    if (mtile < 64) {
        int idx  = mtile * 256 + tid;      // < 16384
        int nt   = idx >> 11;
        int rem  = idx & 2047;
        int drow = rem >> 4;
        int kg   = rem & 15;

        const float* wr = W + (size_t)(nt * 128 + drow) * 128 + kg * 8;
        unsigned hv[4];
        #pragma unroll
        for (int j = 0; j < 4; ++j)
            hv[j] = packh2(__float2half_rn(wr[2 * j]), __float2half_rn(wr[2 * j + 1]));
        unsigned char* base = g_B + (size_t)nt * 32768;
        *reinterpret_cast<uint4*>(base + sw((unsigned)drow, (unsigned)kg * 16)) =
            make_uint4(hv[0], hv[1], hv[2], hv[3]);

        __syncthreads();
        if (tid == 0) { __threadfence(); atomicAdd(&g_flag, 1); }
    }

    // ---- Mask tail for this tile's 128 rows (fused) ----
    if (mask_out != nullptr && tid < 128) {
        int n = n0 + tid;
        mask_out[(size_t)mtile * 128 + tid] = (n < L) ? 1.0f : 0.0f;
    }

    // ---- Fast path: fully-masked tile -> pure zero fill (never blocks 0-63) ----
    if (n0 >= L) {
        float* base = out + (size_t)mtile * 128 * DDIM;
        #pragma unroll 4
        for (int i = tid; i < (128 * DDIM) / 4; i += 256)
            STG_CS_V4Z(base + (size_t)i * 4);
        block_finish(tid);
        return;
    }

    // ---- Generate feats tile (fp16, masked, swizzled) via rotation recurrence ----
    {
        const int row0 = tid >> 4;         // 0..15
        const int kg   = tid & 15;
        const float nf = (float)(n0 + row0);

        float c[4], s[4], C[4], S[4];
        #pragma unroll
        for (int j = 0; j < 4; ++j) {
            int k = kg * 4 + j + 1;
            float Delta = (TWO_PI_F * (float)k) / Lf;
            float theta = nf * Delta;
            float q = rintf(theta * INV_2PI);
            float r = fmaf(-q, PI2_HI, theta);
            r       = fmaf(-q, PI2_LO, r);
            __sincosf(r, &s[j], &c[j]);
            __sincosf(16.0f * Delta, &S[j], &C[j]);
        }

        #pragma unroll
        for (int it = 0; it < 8; ++it) {
            int row = row0 + it * 16;
            int n   = n0 + row;
            float m = (n < L) ? 0.125f : 0.0f;
            unsigned hv[4];
            #pragma unroll
            for (int j = 0; j < 4; ++j)
                hv[j] = packh2(__float2half_rn(c[j] * m), __float2half_rn(s[j] * m));
            *reinterpret_cast<uint4*>(smem + SMEM_A + sw((unsigned)row, (unsigned)kg * 16)) =
                make_uint4(hv[0], hv[1], hv[2], hv[3]);
            #pragma unroll
            for (int j = 0; j < 4; ++j) {
                float cn = fmaf(c[j], C[j], -s[j] * S[j]);
                float sn = fmaf(s[j], C[j],  c[j] * S[j]);
                c[j] = cn; s[j] = sn;
            }
        }
    }

    // ---- Wait for all 64 W chunks (gen above overlapped the wprep wave) ----
    if (tid == 0) {
        while (atomicAdd(&g_flag, 0) < 64) __nanosleep(64);
    }
    __syncthreads();   // A tile ready + W-ready broadcast to the block

    // ---- Prologue: async-copy first B tile ----
    {
        const unsigned char* gB0 = g_B + (size_t)phase * 32768;
        #pragma unroll
        for (int it = 0; it < 8; ++it)
            CP_ASYNC16(sb + SMEM_B + it * 4096 + tid * 16, gB0 + it * 4096 + tid * 16);
        CP_ASYNC_COMMIT();
    }

    // ---- Per-thread ldmatrix address components (warp tile 32 rows x 64 cols) ----
    const unsigned m0 = (unsigned)(wid >> 1) * 32u;   // warp M base (0,32,64,96)
    const unsigned nb = (unsigned)(wid & 1) * 64u;    // warp N base (0,64)
    const unsigned aRow  = m0 + (unsigned)(lane & 15);
    const unsigned aXr   = (aRow & 7u) << 4;
    const unsigned aC0   = (unsigned)(lane & 16);
    const uint32_t aBase0 = sb + SMEM_A + aRow * 256u;
    const uint32_t aBase1 = aBase0 + 16u * 256u;
    const unsigned bRl = (unsigned)((lane & 7) + ((lane & 16) ? 8 : 0));
    const unsigned bXr = (bRl & 7u) << 4;
    const unsigned bC0 = (unsigned)((lane & 8) ? 16 : 0);

    for (int it = 0; it < NT; ++it) {
        const int nt = (it + phase) & 7;

        CP_ASYNC_WAIT0();
        __syncthreads();   // B tile ready; all warps done with the other buffer

        if (it + 1 < NT) {
            const unsigned char* gBn = g_B + (size_t)(((it + 1 + phase) & 7)) * 32768;
            uint32_t bo = sb + SMEM_B + (unsigned)((it + 1) & 1) * 32768u;
            #pragma unroll
            for (int i2 = 0; i2 < 8; ++i2)
                CP_ASYNC16(bo + i2 * 4096 + tid * 16, gBn + i2 * 4096 + tid * 16);
            CP_ASYNC_COMMIT();
        }

        const uint32_t bBase = sb + SMEM_B + (unsigned)(it & 1) * 32768u;

        // acc[0..7]: m-frag 0 (rows m0+q, m0+8+q), acc[8..15]: m-frag 1 (rows +16).
        // acc[8h+i] covers cols [8i, 8i+8) of the warp's 64-col region.
        float acc[16][4];
        #pragma unroll
        for (int i = 0; i < 16; ++i)
            #pragma unroll
            for (int j = 0; j < 4; ++j) acc[i][j] = 0.0f;

        #pragma unroll
        for (int ks = 0; ks < 8; ++ks) {
            const unsigned akb = ((unsigned)ks * 32u + aC0) ^ aXr;
            uint32_t a0[4], a1[4];
            LDSM_X4(a0, aBase0 + akb);
            LDSM_X4(a1, aBase1 + akb);

            const unsigned bkb = ((unsigned)ks * 32u + bC0) ^ bXr;
            #pragma unroll
            for (int np = 0; np < 4; ++np) {
                uint32_t bh[4];
                LDSM_X4(bh, bBase + (nb + np * 16u + bRl) * 256u + bkb);
                MMA16816(acc[np * 2],         a0, bh[0], bh[1]);
                MMA16816(acc[np * 2 + 1],     a0, bh[2], bh[3]);
                MMA16816(acc[8 + np * 2],     a1, bh[0], bh[1]);
                MMA16816(acc[8 + np * 2 + 1], a1, bh[2], bh[3]);
            }
        }

        // ---- Epilogue: butterfly transpose -> STG.cs.128 ----
        {
            const int q   = lane >> 2;
            const int lam = lane & 3;
            const size_t rowbase = ((size_t)(mtile * 128) + m0) * DDIM
                                 + (size_t)nt * 128 + nb + 4 * lam;
            #pragma unroll
            for (int h = 0; h < 2; ++h) {
                #pragma unroll
                for (int ssv = 0; ssv < 2; ++ssv) {
                    float2 v[8];
                    #pragma unroll
                    for (int t = 0; t < 8; ++t) {
                        v[t].x = acc[8 * h + t][2 * ssv];
                        v[t].y = acc[8 * h + t][2 * ssv + 1];
                    }
                    xstage8<1>(v, lane);
                    xstage8<0>(v, lane);
                    float* rp = out + rowbase + (size_t)(16 * h + 8 * ssv + q) * DDIM;
                    #pragma unroll
                    for (int g = 0; g < 4; ++g)
                        STG_CS_V4F(rp + 16 * g,
                                   v[2 * g].x, v[2 * g].y,
                                   v[2 * g + 1].x, v[2 * g + 1].y);
                }
            }
        }
    }

    block_finish(tid);
}

// ---------------------------------------------------------------------------
extern "C" void kernel_launch(void* const* d_in, const int* in_sizes, int n_in,
                              void* d_out, int out_size)
{
    const int*   lengths = (const int*)d_in[0];
    const float* W       = (const float*)d_in[1];
    float*       out     = (float*)d_out;
    (void)in_sizes; (void)n_in;

    cudaFuncSetAttribute(gemm_kernel,
                         cudaFuncAttributeMaxDynamicSharedMemorySize, SMEM_TOTAL);

    long long pos_elems = (long long)MTOT * DDIM;
    float* mask_ptr = ((long long)out_size >= pos_elems + (long long)MTOT)
                          ? (out + pos_elems) : nullptr;

    gemm_kernel<<<MT, 256, SMEM_TOTAL>>>(lengths, W, out, mask_ptr);
}